// round 10
// baseline (speedup 1.0000x reference)
#include <cuda_runtime.h>
#include <cstdint>

#define TT 2048
#define DD 512
#define LCH 32                    // chunk length
#define NCH (TT / LCH)            // 64
#define STEPS 16
#define NBLK (TT / STEPS)         // 128
#define NSTG 4
#define STEP_F 160                // floats per step staged: rt64 kt64 v32
#define STAGE_F (STEPS * STEP_F)  // 2560
#define STAGE_B (STAGE_F * 4)     // 10240
#define PART_F (STEPS * 8 * 36)   // 4608 floats per parity buffer
#define SMEM_FLOATS (NSTG * STAGE_F + 2 * PART_F)   // 19456 floats = 76 KB

// scratch (device globals: no allocation allowed)
__device__ float g_part[(size_t)8 * TT * DD];   // 32 MB y partials
__device__ float g_rt[(size_t)TT * DD];         // r~ = r * P_prev
__device__ float g_kt[(size_t)TT * DD];         // k~ = k / P
__device__ float g_pl[(size_t)NCH * DD];        // per-chunk decay P_L
__device__ float g_A[(size_t)NCH * LCH * LCH];  // masked intra-chunk A

typedef unsigned long long ull;

__device__ __forceinline__ ull pk2(float lo, float hi) {
    ull r; asm("mov.b64 %0,{%1,%2};" : "=l"(r) : "f"(lo), "f"(hi)); return r;
}
__device__ __forceinline__ void up2(ull x, float& lo, float& hi) {
    asm("mov.b64 {%0,%1},%2;" : "=f"(lo), "=f"(hi) : "l"(x));
}
__device__ __forceinline__ ull f2fma(ull a, ull b, ull c) {
    ull d; asm("fma.rn.f32x2 %0,%1,%2,%3;" : "=l"(d) : "l"(a), "l"(b), "l"(c)); return d;
}
__device__ __forceinline__ ull f2mul(ull a, ull b) {
    ull d; asm("mul.rn.f32x2 %0,%1,%2;" : "=l"(d) : "l"(a), "l"(b)); return d;
}
__device__ __forceinline__ ull f2add(ull a, ull b) {
    ull d; asm("add.rn.f32x2 %0,%1,%2;" : "=l"(d) : "l"(a), "l"(b)); return d;
}

#define CP16(dst, src) asm volatile("cp.async.cg.shared.global [%0], [%1], 16;\n" :: "r"(dst), "l"(src))
#define CP_COMMIT()    asm volatile("cp.async.commit_group;\n")
#define CP_WAIT2()     asm volatile("cp.async.wait_group 2;\n" ::: "memory")

// ---------------------------------------------------------------------------
// K1: per-chunk cumulative decay; emit r~, k~, P_L. grid (NCH, 2) x 256.
// ---------------------------------------------------------------------------
__global__ void __launch_bounds__(256) wkv_pre(
    const float* __restrict__ r, const float* __restrict__ w,
    const float* __restrict__ k)
{
    const int a = blockIdx.y * 256 + threadIdx.x;
    const int c = blockIdx.x;
    const size_t base = (size_t)c * LCH * DD + a;
    float P = 1.f;
#pragma unroll 4
    for (int s = 0; s < LCH; s++) {
        const size_t idx = base + (size_t)s * DD;
        const float rv = r[idx], wv = w[idx], kv = k[idx];
        g_rt[idx] = rv * P;
        P = fmaxf(P * wv, 1e-30f);
        g_kt[idx] = kv / P;
    }
    g_pl[(size_t)c * DD + a] = P;
}

// role -> (gmem base, float offset in step slot). 40 roles per step.
__device__ __forceinline__ void cp_role(
    int piece, const float* v, int bx, int by,
    const float*& src, unsigned& foff)
{
    const int stp  = piece / 40;          // step in block (0..15)
    const int role = piece - stp * 40;    // 0..39
    const float* basep; int off;
    if (role < 16) {
        basep = g_rt + by * 64 + role * 4;
        off = role * 4;
    } else if (role < 32) {
        basep = g_kt + by * 64 + (role - 16) * 4;
        off = 64 + (role - 16) * 4;
    } else {
        basep = v + bx * 32 + (role - 32) * 4;
        off = 128 + (role - 32) * 4;
    }
    src  = basep + (size_t)stp * DD;
    foff = (unsigned)(stp * STEP_F + off);
}

// ---------------------------------------------------------------------------
// Sequential kernel. Grid (16,8), 256 thr, 1 CTA/SM. Tile 64x32; warp wid
// owns cols [wid*4,wid*4+4); lane = rg*4+c; thread = 8 rows x 1 col.
// Per chunk (32 steps): S frozen (y-dot reads it), acc += k~*v; at chunk end
// S = P_L*(S+acc). One barrier + one batched reduction per 16 steps.
// ---------------------------------------------------------------------------
__global__ void __launch_bounds__(256, 1) wkv_main(
    const float* __restrict__ v, const float* __restrict__ init_state,
    float* __restrict__ state_out)
{
    extern __shared__ __align__(16) float smem[];
    float* stage = smem;                       // [NSTG][STAGE_F]
    float* partb = smem + NSTG * STAGE_F;      // [2][PART_F]  [st][rg][36]

    const int tid  = threadIdx.x;
    const int bx   = blockIdx.x;
    const int by   = blockIdx.y;
    const int wid  = tid >> 5;
    const int lane = tid & 31;
    const int c    = lane & 3;
    const int rg   = lane >> 2;
    const int col32 = wid * 4 + c;
    const int b    = bx * 32 + col32;
    const int a0   = by * 64 + rg * 8;

    const unsigned smem_u32 = (unsigned)__cvta_generic_to_shared(smem);

    // cp roles: 640 pieces/block; every thread 2, threads<128 get a 3rd
    const bool has3 = (tid < 128);
    const float *s0, *s1, *s2s;
    unsigned o0, o1, o2;
    cp_role(tid,        v, bx, by, s0, o0);
    cp_role(tid + 256,  v, bx, by, s1, o1);
    cp_role(has3 ? tid + 512 : tid, v, bx, by, s2s, o2);
    o0 = smem_u32 + o0 * 4u; o1 = smem_u32 + o1 * 4u; o2 = smem_u32 + o2 * 4u;

    // ---- init state
    const float is0 = init_state[b];
    ull s2[4], acc[4], pl2[4];
    {
        ull iv = pk2(is0, is0);
#pragma unroll
        for (int i = 0; i < 4; i++) { s2[i] = iv; acc[i] = 0ull; }
    }

    // ---- prologue: stage blocks 0,1,2
#pragma unroll
    for (int s = 0; s < 3; s++) {
        const size_t adv = (size_t)s * STEPS * DD;
        const unsigned bo = s * STAGE_B;
        CP16(o0 + bo, s0 + adv);
        CP16(o1 + bo, s1 + adv);
        if (has3) CP16(o2 + bo, s2s + adv);
        CP_COMMIT();
    }
    s0 += (size_t)3 * STEPS * DD; s1 += (size_t)3 * STEPS * DD;
    s2s += (size_t)3 * STEPS * DD;
    CP_WAIT2();
    __syncthreads();

    const int wbase = rg * 36 + col32;
    float* gpr = g_part + (size_t)by * TT * DD + (size_t)bx * 32 + lane;
    const int vidx = 128 + col32;
    const float* plbase = g_pl + a0;

    int gOff  = 0;
    unsigned giOff = 3 * STAGE_B;

    for (int blk = 0; blk < NBLK; blk++) {
        const int p = blk & 1;
        const char* sgb = (const char*)stage + gOff;
        float* pp = partb + p * PART_F;
        float vals[STEPS];

        // prefetch this chunk's P_L at chunk start (used at chunk end)
        if ((blk & 1) == 0) {
            const float4* plp = (const float4*)(plbase + (size_t)(blk >> 1) * DD);
            float4 pa = plp[0], pb = plp[1];
            pl2[0] = pk2(pa.x, pa.y); pl2[1] = pk2(pa.z, pa.w);
            pl2[2] = pk2(pb.x, pb.y); pl2[3] = pk2(pb.z, pb.w);
        }

#pragma unroll
        for (int st = 0; st < STEPS; st++) {
            const ull* sb = (const ull*)(sgb + st * (STEP_F * 4));

            ulonglong2 ra = *reinterpret_cast<const ulonglong2*>(sb + rg * 4);
            ulonglong2 rb = *reinterpret_cast<const ulonglong2*>(sb + rg * 4 + 2);
            ulonglong2 ka = *reinterpret_cast<const ulonglong2*>(sb + 32 + rg * 4);
            ulonglong2 kb = *reinterpret_cast<const ulonglong2*>(sb + 32 + rg * 4 + 2);
            const float vf = ((const float*)sb)[vidx];
            const ull vv = pk2(vf, vf);

            // y_inter partial: r~_t . S_chunkstart (frozen)
            ull p2;
            p2 = f2mul(ra.x, s2[0]);
            p2 = f2fma(ra.y, s2[1], p2);
            p2 = f2fma(rb.x, s2[2], p2);
            p2 = f2fma(rb.y, s2[3], p2);

            // acc += k~ * v
            acc[0] = f2fma(ka.x, vv, acc[0]);
            acc[1] = f2fma(ka.y, vv, acc[1]);
            acc[2] = f2fma(kb.x, vv, acc[2]);
            acc[3] = f2fma(kb.y, vv, acc[3]);

            float pl, ph; up2(p2, pl, ph);
            vals[st] = pl + ph;
        }

        // chunk end: S = P_L * (S + acc)
        if (blk & 1) {
#pragma unroll
            for (int i = 0; i < 4; i++) {
                s2[i] = f2mul(pl2[i], f2add(s2[i], acc[i]));
                acc[i] = 0ull;
            }
        }

        // batched partial write
#pragma unroll
        for (int st = 0; st < STEPS; st++) pp[wbase + st * 288] = vals[st];

        // stage block blk+3
        if (blk + 3 < NBLK) {
            CP16(o0 + giOff, s0);
            CP16(o1 + giOff, s1);
            if (has3) CP16(o2 + giOff, s2s);
        }
        s0 += STEPS * DD; s1 += STEPS * DD; s2s += STEPS * DD;
        CP_COMMIT();
        CP_WAIT2();
        __syncthreads();

        // batched reduction: (col=lane, st=wid) and (st=wid+8)
        {
            const size_t t0 = (size_t)blk * STEPS;
#pragma unroll
            for (int h = 0; h < 2; h++) {
                const int st = wid + h * 8;
                const float* pr = pp + st * 288 + lane;
                float accr = pr[0];
#pragma unroll
                for (int g = 1; g < 8; g++) accr += pr[g * 36];
                gpr[(t0 + st) * DD] = accr;
            }
        }

        gOff  = (gOff  == (NSTG - 1) * STAGE_B) ? 0 : gOff  + STAGE_B;
        giOff = (giOff == (NSTG - 1) * STAGE_B) ? 0 : giOff + STAGE_B;
    }

    // ---- final state
    if (state_out) {
#pragma unroll
        for (int i = 0; i < 4; i++) {
            float lo, hi; up2(s2[i], lo, hi);
            state_out[(size_t)(a0 + 2 * i)     * DD + b] = lo;
            state_out[(size_t)(a0 + 2 * i + 1) * DD + b] = hi;
        }
    }
}

// ---------------------------------------------------------------------------
// A[c][t][s] = r~_t . k~_s  (strict lower triangle, else 0). grid NCH x 256.
// ---------------------------------------------------------------------------
__global__ void __launch_bounds__(256) wkv_amat()
{
    __shared__ float sR[32][68], sK[32][68];
    const int cc = blockIdx.x;
    const int tid = threadIdx.x;
    const int t = tid >> 3, sq = (tid & 7) * 4;
    float acc[4] = {0.f, 0.f, 0.f, 0.f};

    for (int kk = 0; kk < DD; kk += 64) {
        for (int i = tid; i < 32 * 16; i += 256) {
            const int row = i >> 4, col4 = (i & 15) * 4;
            const size_t gidx = (size_t)(cc * LCH + row) * DD + kk + col4;
            *(float4*)&sR[row][col4] = *(const float4*)&g_rt[gidx];
            *(float4*)&sK[row][col4] = *(const float4*)&g_kt[gidx];
        }
        __syncthreads();
        for (int j = 0; j < 64; j++) {
            const float rv = sR[t][j];
            acc[0] += rv * sK[sq + 0][j];
            acc[1] += rv * sK[sq + 1][j];
            acc[2] += rv * sK[sq + 2][j];
            acc[3] += rv * sK[sq + 3][j];
        }
        __syncthreads();
    }
#pragma unroll
    for (int i = 0; i < 4; i++)
        g_A[(size_t)(cc * LCH + t) * LCH + sq + i] = (sq + i < t) ? acc[i] : 0.f;
}

// ---------------------------------------------------------------------------
// Combine: y[t][b] = ruk_t*v[t][b] + sum of 8 row-block partials. grid TT.
// ---------------------------------------------------------------------------
__global__ void __launch_bounds__(256) wkv_combine(
    const float* __restrict__ r, const float* __restrict__ k,
    const float* __restrict__ u, const float* __restrict__ v,
    float* __restrict__ y)
{
    const int t = blockIdx.x;
    const int tid = threadIdx.x;
    __shared__ float red[8];

    const float* rt = r + (size_t)t * DD;
    const float* kt = k + (size_t)t * DD;

    float p = rt[tid] * u[tid] * kt[tid]
            + rt[tid + 256] * u[tid + 256] * kt[tid + 256];
#pragma unroll
    for (int m = 16; m >= 1; m >>= 1) p += __shfl_xor_sync(0xffffffffu, p, m);
    if ((tid & 31) == 0) red[tid >> 5] = p;
    __syncthreads();

    float ruk = 0.f;
#pragma unroll
    for (int g = 0; g < 8; g++) ruk += red[g];

    const float2* v2 = (const float2*)(v + (size_t)t * DD);
    float2* y2 = (float2*)(y + (size_t)t * DD);
    float2 vv = v2[tid];
    float2 acc; acc.x = ruk * vv.x; acc.y = ruk * vv.y;
#pragma unroll
    for (int g = 0; g < 8; g++) {
        const float2* gp2 = (const float2*)(g_part + (size_t)g * TT * DD + (size_t)t * DD);
        float2 pv = gp2[tid];
        acc.x += pv.x; acc.y += pv.y;
    }
    y2[tid] = acc;
}

// ---------------------------------------------------------------------------
// Intra-chunk: y[c*32+t][b] += sum_{s<t} A[c][t][s] * v[c*32+s][b]. grid NCH.
// ---------------------------------------------------------------------------
__global__ void __launch_bounds__(256) wkv_intra(
    const float* __restrict__ v, float* __restrict__ y)
{
    extern __shared__ float sm[];           // V 32x512 + A 32x32
    float* sV = sm;
    float* sA = sm + LCH * DD;
    const int cc = blockIdx.x;
    const int tid = threadIdx.x;

    for (int i = tid; i < LCH * DD / 4; i += 256)
        *(float4*)&sV[i * 4] = *(const float4*)&v[(size_t)cc * LCH * DD + i * 4];
    for (int i = tid; i < LCH * LCH / 4; i += 256)
        *(float4*)&sA[i * 4] = *(const float4*)&g_A[(size_t)cc * LCH * LCH + i * 4];
    __syncthreads();

    const int b = tid * 2;
    for (int t = 1; t < LCH; t++) {
        float a0 = 0.f, a1 = 0.f;
        for (int s = 0; s < t; s++) {
            const float av = sA[t * LCH + s];
            a0 += av * sV[s * DD + b];
            a1 += av * sV[s * DD + b + 1];
        }
        const size_t yi = (size_t)(cc * LCH + t) * DD + b;
        y[yi]     += a0;
        y[yi + 1] += a1;
    }
}

// ---------------------------------------------------------------------------
extern "C" void kernel_launch(void* const* d_in, const int* in_sizes, int n_in,
                              void* d_out, int out_size) {
    const float* r          = (const float*)d_in[0];
    const float* w          = (const float*)d_in[1];
    const float* k          = (const float*)d_in[2];
    const float* v          = (const float*)d_in[3];
    const float* init_state = (const float*)d_in[4];
    const float* u          = (const float*)d_in[5];
    float* out = (float*)d_out;

    const int NTD = TT * DD;
    const int NDD = DD * DD;

    float* y  = nullptr;
    float* st = nullptr;
    if (out_size >= NTD) {
        y = out;
        if (out_size >= NTD + NDD) st = out + NTD;
    } else if (out_size == NDD) {
        st = out;
    }

    const int smem_main  = SMEM_FLOATS * 4;            // 77824
    const int smem_intra = (LCH * DD + LCH * LCH) * 4; // 69632
    // Unconditional (no static guard — harness forbids call-count state);
    // idempotent host-side calls, legal under graph capture.
    cudaFuncSetAttribute(wkv_main, cudaFuncAttributeMaxDynamicSharedMemorySize, smem_main);
    cudaFuncSetAttribute(wkv_intra, cudaFuncAttributeMaxDynamicSharedMemorySize, smem_intra);

    wkv_pre<<<dim3(NCH, 2), 256>>>(r, w, k);
    wkv_main<<<dim3(16, 8), 256, smem_main>>>(v, init_state, st);
    if (y) {
        wkv_amat<<<NCH, 256>>>();
        wkv_combine<<<TT, 256>>>(r, k, u, v, y);
        wkv_intra<<<NCH, 256, smem_intra>>>(v, y);
    }
}